// round 13
// baseline (speedup 1.0000x reference)
#include <cuda_runtime.h>
#include <cuda_fp16.h>
#include <cstdint>

#define HD 32
#define EE 128
#define DS 512
#define BB 8
#define NLQ 1024
#define NLK 1024

// ---------------- device scratch (allocation-free rule) ----------------
__device__ uint32_t g_K  [(size_t)HD * BB * 16 * 4096];  // K*scale+bk  [hb][chunk][nb8][ksb8][lane][2]
__device__ uint32_t g_Vt [(size_t)HD * BB * 16 * 4096];  // V'          [hb][chunk][nb16][ksb4][lane][2]
__device__ uint32_t g_Sf [(size_t)BB * 8 * 8 * 4096];    // states      [b][mt][kc][mb8][ksb4][lane][4]
__device__ uint32_t g_Wkf[(size_t)HD * 8 * 4096];        // Wk^T frag   [h][kc][nb16][ksb4][lane][2]
__device__ uint32_t g_Wvf[(size_t)HD * 8 * 4096];        // (Wv@Wo)^T frag
__device__ float g_Cbias[EE];
__device__ uint32_t g_OpartH[(size_t)HD * BB * NLQ * 64];  // fp16 head partials (half2)

// ---------------- helpers ----------------
__device__ __forceinline__ uint32_t smem_u32(const void* p) {
    uint32_t a;
    asm("{ .reg .u64 t; cvta.to.shared.u64 t, %1; cvt.u32.u64 %0, t; }"
        : "=r"(a) : "l"(p));
    return a;
}
__device__ __forceinline__ uint32_t pack2(float a, float b) {
    __half2 h = __floats2half2_rn(a, b);
    return *reinterpret_cast<uint32_t*>(&h);
}
__device__ __forceinline__ void mma16(float* d, const uint32_t* a, const uint32_t* b) {
    asm volatile("mma.sync.aligned.m16n8k16.row.col.f32.f16.f16.f32 "
                 "{%0,%1,%2,%3}, {%4,%5,%6,%7}, {%8,%9}, {%0,%1,%2,%3};"
                 : "+f"(d[0]), "+f"(d[1]), "+f"(d[2]), "+f"(d[3])
                 : "r"(a[0]), "r"(a[1]), "r"(a[2]), "r"(a[3]),
                   "r"(b[0]), "r"(b[1]));
}
// fp16-accumulate variant (D/C in half2 words); used for S only
__device__ __forceinline__ void mma16h(uint32_t* d, const uint32_t* a, const uint32_t* b) {
    asm volatile("mma.sync.aligned.m16n8k16.row.col.f16.f16.f16.f16 "
                 "{%0,%1}, {%2,%3,%4,%5}, {%6,%7}, {%0,%1};"
                 : "+r"(d[0]), "+r"(d[1])
                 : "r"(a[0]), "r"(a[1]), "r"(a[2]), "r"(a[3]),
                   "r"(b[0]), "r"(b[1]));
}
__device__ __forceinline__ void cp16(uint32_t dst, const void* src) {
    asm volatile("cp.async.cg.shared.global [%0], [%1], 16;" :: "r"(dst), "l"(src));
}
__device__ __forceinline__ void cp_commit() {
    asm volatile("cp.async.commit_group;" ::: "memory");
}
// copy one 4096-u32 (16KB) fragment chunk, 256 threads
__device__ __forceinline__ void cp_chunk(uint32_t smb, int soff,
                                         const uint32_t* gsrc, int tid) {
#pragma unroll
    for (int i = 0; i < 4; i++) {
        const int idx = tid + i * 256;
        cp16(smb + (uint32_t)(soff + idx * 4) * 4, gsrc + (size_t)idx * 4);
    }
}

// ---------------- fused WvWo GEMM -> fragment-major pack ----------------
__global__ __launch_bounds__(256) void k_wvwo(const float* __restrict__ Wv,
                                              const float* __restrict__ Wo)
{
    __shared__ float As[64][16];
    __shared__ float Bs[16][128];
    __shared__ float st[64][132];
    const int mt = blockIdx.x, h = blockIdx.y;
    const float* A = Wv + (size_t)h * DS * EE + (size_t)mt * 64 * EE;
    const float* B = Wo + (size_t)h * EE * EE;
    const int tid = threadIdx.x;
    const int tx = tid & 15, ty = tid >> 4;
    float acc[4][8];
#pragma unroll
    for (int i = 0; i < 4; i++)
#pragma unroll
        for (int j = 0; j < 8; j++) acc[i][j] = 0.f;
    const int arow = tid >> 2, ac4 = (tid & 3) << 2;
    const int brow = tid >> 4, bc = (tid & 15) << 3;
    for (int k0 = 0; k0 < EE; k0 += 16) {
        __syncthreads();
        *(float4*)&As[arow][ac4] = *(const float4*)&A[(size_t)arow * EE + k0 + ac4];
        *(float4*)&Bs[brow][bc] = *(const float4*)&B[(size_t)(k0 + brow) * EE + bc];
        *(float4*)&Bs[brow][bc + 4] = *(const float4*)&B[(size_t)(k0 + brow) * EE + bc + 4];
        __syncthreads();
#pragma unroll
        for (int kk = 0; kk < 16; kk++) {
            float a[4], bb[8];
#pragma unroll
            for (int i = 0; i < 4; i++) a[i] = As[ty * 4 + i][kk];
#pragma unroll
            for (int j = 0; j < 8; j++) bb[j] = Bs[kk][tx + 16 * j];
#pragma unroll
            for (int i = 0; i < 4; i++)
#pragma unroll
                for (int j = 0; j < 8; j++) acc[i][j] += a[i] * bb[j];
        }
    }
#pragma unroll
    for (int i = 0; i < 4; i++)
#pragma unroll
        for (int j = 0; j < 8; j++)
            st[ty * 4 + i][tx + 16 * j] = acc[i][j];
    __syncthreads();
    uint32_t* dst = g_Wvf + ((size_t)h * 8 + mt) * 4096;
    for (int s = tid; s < 2048; s += 256) {
        const int nb = s >> 7, ksb = (s >> 5) & 3, ln = s & 31;
        const int e = nb * 8 + (ln >> 2);
        const int d0 = ksb * 16 + (ln & 3) * 2;
        uint2 v;
        v.x = pack2(st[d0][e],     st[d0 + 1][e]);
        v.y = pack2(st[d0 + 8][e], st[d0 + 9][e]);
        *(uint2*)(dst + (size_t)s * 2) = v;
    }
}

// fused constant bias: Cbias[e] = bo[e] + sum_h bv[h]@Wo_h[:,e]
__global__ void k_cbias(const float* __restrict__ bv, const float* __restrict__ Wo,
                        const float* __restrict__ bo)
{
    const int e = blockIdx.x, t = threadIdx.x;
    float acc = 0.f;
    for (int idx = t; idx < HD * EE; idx += 32)
        acc += bv[idx] * Wo[(size_t)idx * EE + e];
#pragma unroll
    for (int off = 16; off >= 1; off >>= 1)
        acc += __shfl_xor_sync(0xffffffffu, acc, off);
    if (t == 0) g_Cbias[e] = bo[e] + acc;
}

// ---------------- pack states -> A-fragment-major fp16 ----------------
__global__ __launch_bounds__(256) void k_packS(const float* __restrict__ states)
{
    __shared__ float st[128][68];
    const int kc = blockIdx.x, mt = blockIdx.y, b = blockIdx.z;
    const int tid = threadIdx.x;
    const float* src = states + ((size_t)b * NLK + mt * 128) * DS + kc * 64;
    for (int i = tid; i < 128 * 16; i += 256) {
        const int r = i >> 4, c4 = (i & 15) << 2;
        *(float4*)&st[r][c4] = *(const float4*)(src + (size_t)r * DS + c4);
    }
    __syncthreads();
    uint32_t* dst = g_Sf + (((size_t)b * 8 + mt) * 8 + kc) * 4096;
    for (int s = tid; s < 1024; s += 256) {
        const int mb = s >> 7, ksb = (s >> 5) & 3, ln = s & 31;
        const int m0 = mb * 16 + (ln >> 2);
        const int k0 = ksb * 16 + (ln & 3) * 2;
        uint4 v;
        v.x = pack2(st[m0][k0],         st[m0][k0 + 1]);
        v.y = pack2(st[m0 + 8][k0],     st[m0 + 8][k0 + 1]);
        v.z = pack2(st[m0][k0 + 8],     st[m0][k0 + 9]);
        v.w = pack2(st[m0 + 8][k0 + 8], st[m0 + 8][k0 + 9]);
        *(uint4*)(dst + (size_t)s * 4) = v;
    }
}

// ---------------- pack Wk^T -> B-fragment-major fp16 ----------------
__global__ __launch_bounds__(256) void k_packW(const float* __restrict__ Wk)
{
    __shared__ float st[64][132];
    const int kc = blockIdx.x, h = blockIdx.y;
    const int tid = threadIdx.x;
    const float* src = Wk + (size_t)h * DS * EE + (size_t)kc * 64 * EE;
    for (int i = tid; i < 64 * 32; i += 256) {
        const int d = i >> 5, e4 = (i & 31) << 2;
        *(float4*)&st[d][e4] = *(const float4*)(src + (size_t)d * EE + e4);
    }
    __syncthreads();
    uint32_t* dst = g_Wkf + ((size_t)h * 8 + kc) * 4096;
    for (int s = tid; s < 2048; s += 256) {
        const int nb = s >> 7, ksb = (s >> 5) & 3, ln = s & 31;
        const int e = nb * 8 + (ln >> 2);
        const int d0 = ksb * 16 + (ln & 3) * 2;
        uint2 v;
        v.x = pack2(st[d0][e],     st[d0 + 1][e]);
        v.y = pack2(st[d0 + 8][e], st[d0 + 9][e]);
        *(uint2*)(dst + (size_t)s * 2) = v;
    }
}

// ---------------- projection kernel (fp16 mma, 1 barrier per chunk) ----------------
#define PROJ_SMEM 69632

__global__ __launch_bounds__(256, 2) void k_proj(const float* __restrict__ bk)
{
    extern __shared__ uint32_t sm[];
    const uint32_t smb = smem_u32(sm);
    const int tid = threadIdx.x, w = tid >> 5, lane = tid & 31;
    const int gg = lane >> 2, tig = lane & 3;
    const int wm = w >> 2, wn = w & 3;
    const int mt = blockIdx.x;
    const int h = blockIdx.y >> 3, b = blockIdx.y & 7;
    const int kind = blockIdx.z;

    const uint32_t* Asrc = g_Sf + (((size_t)b * 8 + mt) * 8) * 4096;
    const uint32_t* Bsrc = (kind ? g_Wvf : g_Wkf) + (size_t)h * 8 * 4096;

    float acc[4][4][4];
#pragma unroll
    for (int mi = 0; mi < 4; mi++)
#pragma unroll
        for (int ni = 0; ni < 4; ni++)
#pragma unroll
            for (int q = 0; q < 4; q++) acc[mi][ni][q] = 0.f;

    cp_chunk(smb, 0,    Asrc, tid);
    cp_chunk(smb, 8192, Bsrc, tid);
    cp_commit();

    for (int kc = 0; kc < 8; kc++) {
        asm volatile("cp.async.wait_group 0;" ::: "memory");
        __syncthreads();   // chunk kc visible; buffer (kc+1)&1 free (read last at kc-1)
        if (kc < 7) {
            cp_chunk(smb, ((kc + 1) & 1) * 4096,        Asrc + (size_t)(kc + 1) * 4096, tid);
            cp_chunk(smb, 8192 + ((kc + 1) & 1) * 4096, Bsrc + (size_t)(kc + 1) * 4096, tid);
            cp_commit();
        }
        const uint32_t* Ab = sm + (kc & 1) * 4096;
        const uint32_t* Bb = sm + 8192 + (kc & 1) * 4096;
#pragma unroll
        for (int ksb = 0; ksb < 4; ksb++) {
            uint32_t af[4][4], bf[4][2];
#pragma unroll
            for (int mi = 0; mi < 4; mi++)
                *(uint4*)af[mi] = *(const uint4*)(Ab + (((wm * 4 + mi) * 4 + ksb) * 32 + lane) * 4);
#pragma unroll
            for (int ni = 0; ni < 4; ni++)
                *(uint2*)bf[ni] = *(const uint2*)(Bb + (((wn * 4 + ni) * 4 + ksb) * 32 + lane) * 2);
#pragma unroll
            for (int mi = 0; mi < 4; mi++)
#pragma unroll
                for (int ni = 0; ni < 4; ni++)
                    mma16(acc[mi][ni], af[mi], bf[ni]);
        }
    }
    __syncthreads();   // all warps done with smem before epilogue reuse

    const float kscale = 0.08838834764831845f;   // 1/sqrt(128), folded into K

    if (kind == 0) {
        // DIRECT register->global epilogue for K (lane mapping is identity)
        uint32_t* dst = g_K + ((size_t)(h * BB + b) * 16 + mt * 2 + wm) * 4096;
#pragma unroll
        for (int mi = 0; mi < 4; mi++) {
#pragma unroll
            for (int ni2 = 0; ni2 < 2; ni2++) {
                const int ksb = wn * 2 + ni2;
                const int cc0 = wn * 32 + ni2 * 16 + 2 * tig;
                const int cc1 = cc0 + 8;
                const float b00 = bk[h * EE + cc0], b01 = bk[h * EE + cc0 + 1];
                const float b10 = bk[h * EE + cc1], b11 = bk[h * EE + cc1 + 1];
                const float* a0 = acc[mi][2 * ni2];
                const float* a1 = acc[mi][2 * ni2 + 1];
                uint2 v0, v1;
                v0.x = pack2((a0[0] + b00) * kscale, (a0[1] + b01) * kscale);
                v0.y = pack2((a1[0] + b10) * kscale, (a1[1] + b11) * kscale);
                v1.x = pack2((a0[2] + b00) * kscale, (a0[3] + b01) * kscale);
                v1.y = pack2((a1[2] + b10) * kscale, (a1[3] + b11) * kscale);
                *(uint2*)(dst + (((2 * mi) * 8 + ksb) * 32 + lane) * 2) = v0;
                *(uint2*)(dst + (((2 * mi + 1) * 8 + ksb) * 32 + lane) * 2) = v1;
            }
        }
    } else {
        // V' needs a transpose -> stage fp32 [128][131] then pack
        float* st = (float*)sm;
#pragma unroll
        for (int mi = 0; mi < 4; mi++) {
            const int r = wm * 64 + mi * 16 + gg;
#pragma unroll
            for (int ni = 0; ni < 4; ni++) {
                const int cc = wn * 32 + ni * 8 + 2 * tig;
                st[r * 131 + cc]           = acc[mi][ni][0];
                st[r * 131 + cc + 1]       = acc[mi][ni][1];
                st[(r + 8) * 131 + cc]     = acc[mi][ni][2];
                st[(r + 8) * 131 + cc + 1] = acc[mi][ni][3];
            }
        }
        __syncthreads();
        uint32_t* dst = g_Vt + ((size_t)(h * BB + b) * 16 + mt * 2) * 4096;
        for (int s = tid; s < 4096; s += 256) {
            const int lc = s >> 11, rem = s & 2047;
            const int nb = rem >> 7, ksb = (rem >> 5) & 3, ln = rem & 31;
            const int e = nb * 8 + (ln >> 2);
            const int t0 = lc * 64 + ksb * 16 + (ln & 3) * 2;
            uint2 v;
            v.x = pack2(st[t0 * 131 + e],       st[(t0 + 1) * 131 + e]);
            v.y = pack2(st[(t0 + 8) * 131 + e], st[(t0 + 9) * 131 + e]);
            *(uint2*)(dst + (size_t)lc * 4096 + ((nb * 4 + ksb) * 32 + ln) * 2) = v;
        }
    }
}

// ---------------- fused attention kernel ----------------
// Each warp owns a full 16-row band: S = [16 x 64] fp16 acc, O = [16 x 128] fp32 acc.
// Q fragments packed warp-privately straight from gmem (no barriers).
// K and V prefetched in SEPARATE commit groups: S waits only on K.
// smem (u32): Qf [0,8192) | K0 [8192,12288) K1 [12288,16384) | V0 [16384,20480) V1 [20480,24576)
#define QF_OFF 0
#define KB_OFF 8192
#define VB_OFF 16384
#define ATTN_SMEM (24576 * 4)   // 98304 B

__global__ __launch_bounds__(256, 2) void k_attn(const float* __restrict__ query)
{
    extern __shared__ uint32_t sm[];
    const uint32_t smb = smem_u32(sm);
    const int tid = threadIdx.x, w = tid >> 5, lane = tid & 31;
    const int gg = lane >> 2, tig = lane & 3;
    const int qt = blockIdx.x, b = blockIdx.y, h = blockIdx.z;
    const int q0 = qt * 128;

    const uint32_t* Ksrc = g_K  + (size_t)(h * BB + b) * 16 * 4096;
    const uint32_t* Vsrc = g_Vt + (size_t)(h * BB + b) * 16 * 4096;

    // prefetch chunk 0 (K group, then V group)
    cp_chunk(smb, KB_OFF, Ksrc, tid);
    cp_commit();
    cp_chunk(smb, VB_OFF, Vsrc, tid);
    cp_commit();

    // warp-private Q fragment pack: straight gmem -> fragments -> Qf block mb=w.
    // No cross-warp sharing (S phase reads only mb=w), so no barriers needed.
    {
        const float* qrow0 = query + ((size_t)(b * NLQ + q0 + w * 16 + gg)) * EE;
        const float* qrow1 = qrow0 + 8 * EE;
#pragma unroll
        for (int ksb = 0; ksb < 8; ksb++) {
            const int k0 = ksb * 16 + tig * 2;
            const float2 a0 = *(const float2*)(qrow0 + k0);
            const float2 a1 = *(const float2*)(qrow1 + k0);
            const float2 a2 = *(const float2*)(qrow0 + k0 + 8);
            const float2 a3 = *(const float2*)(qrow1 + k0 + 8);
            uint4 v;
            v.x = pack2(a0.x, a0.y);
            v.y = pack2(a1.x, a1.y);
            v.z = pack2(a2.x, a2.y);
            v.w = pack2(a3.x, a3.y);
            *(uint4*)(sm + QF_OFF + ((w * 8 + ksb) * 32 + lane) * 4) = v;
        }
    }

    float oacc[16][4];
#pragma unroll
    for (int nb = 0; nb < 16; nb++)
#pragma unroll
        for (int q = 0; q < 4; q++) oacc[nb][q] = 0.f;
    float ls0 = 0.f, ls1 = 0.f;   // per-tig partial row sums (reduced after loop)

    for (int c = 0; c < 16; c++) {
        // wait for K(c); V(c) may still be in flight (completed before PV below)
        asm volatile("cp.async.wait_group 1;" ::: "memory");
        __syncthreads();   // K(c) visible; buffers (c+1)&1 free for prefetch
        if (c < 15) {
            cp_chunk(smb, KB_OFF + ((c + 1) & 1) * 4096, Ksrc + (size_t)(c + 1) * 4096, tid);
            cp_commit();
            cp_chunk(smb, VB_OFF + ((c + 1) & 1) * 4096, Vsrc + (size_t)(c + 1) * 4096, tid);
            cp_commit();
        }
        const uint32_t* Kb = sm + KB_OFF + (c & 1) * 4096;
        const uint32_t* Vb = sm + VB_OFF + (c & 1) * 4096;

        // ---- S = Q K^T (fp16 accumulate) : this warp's 16-row band x 64 cols ----
        uint32_t sacc[8][2];
#pragma unroll
        for (int nb = 0; nb < 8; nb++) { sacc[nb][0] = 0u; sacc[nb][1] = 0u; }
#pragma unroll
        for (int ksb = 0; ksb < 8; ksb++) {
            uint32_t aq[4];
            *(uint4*)aq = *(const uint4*)(sm + QF_OFF + ((w * 8 + ksb) * 32 + lane) * 4);
#pragma unroll
            for (int nb = 0; nb < 8; nb++) {
                uint32_t bf[2];
                *(uint2*)bf = *(const uint2*)(Kb + ((nb * 8 + ksb) * 32 + lane) * 2);
                mma16h(sacc[nb], aq, bf);
            }
        }

        // ---- P = exp(S) in registers; accumulate per-tig partial row sums ----
        uint32_t pf[16];
#pragma unroll
        for (int nb = 0; nb < 8; nb++) {
            const float2 f0 = __half22float2(*reinterpret_cast<__half2*>(&sacc[nb][0]));
            const float2 f1 = __half22float2(*reinterpret_cast<__half2*>(&sacc[nb][1]));
            const float e0 = __expf(f0.x);
            const float e1 = __expf(f0.y);
            const float e2 = __expf(f1.x);
            const float e3 = __expf(f1.y);
            ls0 += e0 + e1;
            ls1 += e2 + e3;
            pf[nb * 2]     = pack2(e0, e1);   // row r pair
            pf[nb * 2 + 1] = pack2(e2, e3);   // row r+8 pair
        }

        // ensure V(c) has landed (outstanding: V(c), K(c+1), V(c+1) -> wait<=2;
        // last chunk has only V(15) outstanding -> wait 0)
        if (c < 15) {
            asm volatile("cp.async.wait_group 2;" ::: "memory");
        } else {
            asm volatile("cp.async.wait_group 0;" ::: "memory");
        }

        // ---- O += P @ V' (fp32 accumulate) : P a-frags straight from registers ----
#pragma unroll
        for (int ksb = 0; ksb < 4; ksb++) {
            uint32_t af[4] = { pf[ksb * 4], pf[ksb * 4 + 1],
                               pf[ksb * 4 + 2], pf[ksb * 4 + 3] };
#pragma unroll
            for (int nb = 0; nb < 16; nb++) {
                uint32_t bf[2];
                *(uint2*)bf = *(const uint2*)(Vb + ((nb * 4 + ksb) * 32 + lane) * 2);
                mma16(oacc[nb], af, bf);
            }
        }
    }

    // single deferred shuffle reduction of row sums over tig lanes
    ls0 += __shfl_xor_sync(0xffffffffu, ls0, 1);
    ls0 += __shfl_xor_sync(0xffffffffu, ls0, 2);
    ls1 += __shfl_xor_sync(0xffffffffu, ls1, 1);
    ls1 += __shfl_xor_sync(0xffffffffu, ls1, 2);

    // epilogue: normalize by row sums, store fp16 head partial (half2 words)
    uint32_t* Op = g_OpartH + ((size_t)(h * BB + b) * NLQ + q0) * 64;
    const float i0 = 1.f / ls0;
    const float i1 = 1.f / ls1;
    const int r = w * 16 + gg;
#pragma unroll
    for (int nb = 0; nb < 16; nb++) {
        const int cc = nb * 8 + 2 * tig;   // even
        Op[(size_t)r * 64 + (cc >> 1)] =
            pack2(oacc[nb][0] * i0, oacc[nb][1] * i0);
        Op[(size_t)(r + 8) * 64 + (cc >> 1)] =
            pack2(oacc[nb][2] * i1, oacc[nb][3] * i1);
    }
}

// ---------------- final reduce over 32 fp16 head partials ----------------
__global__ void k_reduce(float* __restrict__ out)
{
    const size_t i4 = (size_t)blockIdx.x * blockDim.x + threadIdx.x;
    const size_t base = i4 * 4;             // 4 floats = 2 half2 words
    const int e = (int)(base & 127);
    float s0 = g_Cbias[e],     s1 = g_Cbias[e + 1];
    float s2 = g_Cbias[e + 2], s3 = g_Cbias[e + 3];
    const size_t st = (size_t)BB * NLQ * 64;
#pragma unroll
    for (int hh = 0; hh < HD; hh++) {
        const uint2 t = *(const uint2*)&g_OpartH[(size_t)hh * st + (base >> 1)];
        const __half2 a = *reinterpret_cast<const __half2*>(&t.x);
        const __half2 bb = *reinterpret_cast<const __half2*>(&t.y);
        const float2 fa = __half22float2(a);
        const float2 fb = __half22float2(bb);
        s0 += fa.x; s1 += fa.y; s2 += fb.x; s3 += fb.y;
    }
    *(float4*)&out[base] = make_float4(s0, s1, s2, s3);
}

// ---------------- launch ----------------
extern "C" void kernel_launch(void* const* d_in, const int* in_sizes, int n_in,
                              void* d_out, int out_size)
{
    const float* query  = (const float*)d_in[0];
    const float* states = (const float*)d_in[1];
    const float* Wk     = (const float*)d_in[2];
    const float* bk     = (const float*)d_in[3];
    const float* Wv     = (const float*)d_in[4];
    const float* bv     = (const float*)d_in[5];
    const float* Wo     = (const float*)d_in[6];
    const float* bo     = (const float*)d_in[7];
    float* out = (float*)d_out;

    cudaFuncSetAttribute(k_proj, cudaFuncAttributeMaxDynamicSharedMemorySize, PROJ_SMEM);
    cudaFuncSetAttribute(k_attn, cudaFuncAttributeMaxDynamicSharedMemorySize, ATTN_SMEM);

    k_wvwo<<<dim3(8, HD), 256>>>(Wv, Wo);
    k_cbias<<<EE, 32>>>(bv, Wo, bo);
    k_packS<<<dim3(8, 8, BB), 256>>>(states);
    k_packW<<<dim3(8, HD), 256>>>(Wk);
    k_proj<<<dim3(8, 256, 2), 256, PROJ_SMEM>>>(bk);
    k_attn<<<dim3(8, BB, HD), 256, ATTN_SMEM>>>(query);
    k_reduce<<<(BB * NLQ * EE / 4) / 256, 256>>>(out);
}

// round 14
// speedup vs baseline: 1.0489x; 1.0489x over previous
#include <cuda_runtime.h>
#include <cuda_fp16.h>
#include <cstdint>

#define HD 32
#define EE 128
#define DS 512
#define BB 8
#define NLQ 1024
#define NLK 1024

// ---------------- device scratch (allocation-free rule) ----------------
__device__ uint32_t g_K  [(size_t)HD * BB * 16 * 4096];  // K*scale+bk  [hb][chunk][nb8][ksb8][lane][2]
__device__ uint32_t g_Vt [(size_t)HD * BB * 16 * 4096];  // V'          [hb][chunk][nb16][ksb4][lane][2]
__device__ uint32_t g_Sf [(size_t)BB * 8 * 8 * 4096];    // states      [b][mt][kc][mb8][ksb4][lane][4]
__device__ uint32_t g_Wkf[(size_t)HD * 8 * 4096];        // Wk^T frag   [h][kc][nb16][ksb4][lane][2]
__device__ uint32_t g_Wvf[(size_t)HD * 8 * 4096];        // (Wv@Wo)^T frag
__device__ float g_Cbias[EE];
__device__ uint32_t g_OpartH[(size_t)HD * BB * NLQ * 64];  // fp16 head partials (half2)

// ---------------- helpers ----------------
__device__ __forceinline__ uint32_t smem_u32(const void* p) {
    uint32_t a;
    asm("{ .reg .u64 t; cvta.to.shared.u64 t, %1; cvt.u32.u64 %0, t; }"
        : "=r"(a) : "l"(p));
    return a;
}
__device__ __forceinline__ uint32_t pack2(float a, float b) {
    __half2 h = __floats2half2_rn(a, b);
    return *reinterpret_cast<uint32_t*>(&h);
}
__device__ __forceinline__ void mma16(float* d, const uint32_t* a, const uint32_t* b) {
    asm volatile("mma.sync.aligned.m16n8k16.row.col.f32.f16.f16.f32 "
                 "{%0,%1,%2,%3}, {%4,%5,%6,%7}, {%8,%9}, {%0,%1,%2,%3};"
                 : "+f"(d[0]), "+f"(d[1]), "+f"(d[2]), "+f"(d[3])
                 : "r"(a[0]), "r"(a[1]), "r"(a[2]), "r"(a[3]),
                   "r"(b[0]), "r"(b[1]));
}
// fp16-accumulate variant (D/C in half2 words); used for S only
__device__ __forceinline__ void mma16h(uint32_t* d, const uint32_t* a, const uint32_t* b) {
    asm volatile("mma.sync.aligned.m16n8k16.row.col.f16.f16.f16.f16 "
                 "{%0,%1}, {%2,%3,%4,%5}, {%6,%7}, {%0,%1};"
                 : "+r"(d[0]), "+r"(d[1])
                 : "r"(a[0]), "r"(a[1]), "r"(a[2]), "r"(a[3]),
                   "r"(b[0]), "r"(b[1]));
}
__device__ __forceinline__ void cp16(uint32_t dst, const void* src) {
    asm volatile("cp.async.cg.shared.global [%0], [%1], 16;" :: "r"(dst), "l"(src));
}
__device__ __forceinline__ void cp_commit() {
    asm volatile("cp.async.commit_group;" ::: "memory");
}
// copy one 4096-u32 (16KB) fragment chunk, 256 threads
__device__ __forceinline__ void cp_chunk(uint32_t smb, int soff,
                                         const uint32_t* gsrc, int tid) {
#pragma unroll
    for (int i = 0; i < 4; i++) {
        const int idx = tid + i * 256;
        cp16(smb + (uint32_t)(soff + idx * 4) * 4, gsrc + (size_t)idx * 4);
    }
}

// ---------------- fused WvWo GEMM -> fragment-major pack ----------------
__global__ __launch_bounds__(256) void k_wvwo(const float* __restrict__ Wv,
                                              const float* __restrict__ Wo)
{
    __shared__ float As[64][16];
    __shared__ float Bs[16][128];
    __shared__ float st[64][132];
    const int mt = blockIdx.x, h = blockIdx.y;
    const float* A = Wv + (size_t)h * DS * EE + (size_t)mt * 64 * EE;
    const float* B = Wo + (size_t)h * EE * EE;
    const int tid = threadIdx.x;
    const int tx = tid & 15, ty = tid >> 4;
    float acc[4][8];
#pragma unroll
    for (int i = 0; i < 4; i++)
#pragma unroll
        for (int j = 0; j < 8; j++) acc[i][j] = 0.f;
    const int arow = tid >> 2, ac4 = (tid & 3) << 2;
    const int brow = tid >> 4, bc = (tid & 15) << 3;
    for (int k0 = 0; k0 < EE; k0 += 16) {
        __syncthreads();
        *(float4*)&As[arow][ac4] = *(const float4*)&A[(size_t)arow * EE + k0 + ac4];
        *(float4*)&Bs[brow][bc] = *(const float4*)&B[(size_t)(k0 + brow) * EE + bc];
        *(float4*)&Bs[brow][bc + 4] = *(const float4*)&B[(size_t)(k0 + brow) * EE + bc + 4];
        __syncthreads();
#pragma unroll
        for (int kk = 0; kk < 16; kk++) {
            float a[4], bb[8];
#pragma unroll
            for (int i = 0; i < 4; i++) a[i] = As[ty * 4 + i][kk];
#pragma unroll
            for (int j = 0; j < 8; j++) bb[j] = Bs[kk][tx + 16 * j];
#pragma unroll
            for (int i = 0; i < 4; i++)
#pragma unroll
                for (int j = 0; j < 8; j++) acc[i][j] += a[i] * bb[j];
        }
    }
#pragma unroll
    for (int i = 0; i < 4; i++)
#pragma unroll
        for (int j = 0; j < 8; j++)
            st[ty * 4 + i][tx + 16 * j] = acc[i][j];
    __syncthreads();
    uint32_t* dst = g_Wvf + ((size_t)h * 8 + mt) * 4096;
    for (int s = tid; s < 2048; s += 256) {
        const int nb = s >> 7, ksb = (s >> 5) & 3, ln = s & 31;
        const int e = nb * 8 + (ln >> 2);
        const int d0 = ksb * 16 + (ln & 3) * 2;
        uint2 v;
        v.x = pack2(st[d0][e],     st[d0 + 1][e]);
        v.y = pack2(st[d0 + 8][e], st[d0 + 9][e]);
        *(uint2*)(dst + (size_t)s * 2) = v;
    }
}

// fused constant bias: Cbias[e] = bo[e] + sum_h bv[h]@Wo_h[:,e]
__global__ void k_cbias(const float* __restrict__ bv, const float* __restrict__ Wo,
                        const float* __restrict__ bo)
{
    const int e = blockIdx.x, t = threadIdx.x;
    float acc = 0.f;
    for (int idx = t; idx < HD * EE; idx += 32)
        acc += bv[idx] * Wo[(size_t)idx * EE + e];
#pragma unroll
    for (int off = 16; off >= 1; off >>= 1)
        acc += __shfl_xor_sync(0xffffffffu, acc, off);
    if (t == 0) g_Cbias[e] = bo[e] + acc;
}

// ---------------- pack states -> A-fragment-major fp16 ----------------
__global__ __launch_bounds__(256) void k_packS(const float* __restrict__ states)
{
    __shared__ float st[128][68];
    const int kc = blockIdx.x, mt = blockIdx.y, b = blockIdx.z;
    const int tid = threadIdx.x;
    const float* src = states + ((size_t)b * NLK + mt * 128) * DS + kc * 64;
    for (int i = tid; i < 128 * 16; i += 256) {
        const int r = i >> 4, c4 = (i & 15) << 2;
        *(float4*)&st[r][c4] = *(const float4*)(src + (size_t)r * DS + c4);
    }
    __syncthreads();
    uint32_t* dst = g_Sf + (((size_t)b * 8 + mt) * 8 + kc) * 4096;
    for (int s = tid; s < 1024; s += 256) {
        const int mb = s >> 7, ksb = (s >> 5) & 3, ln = s & 31;
        const int m0 = mb * 16 + (ln >> 2);
        const int k0 = ksb * 16 + (ln & 3) * 2;
        uint4 v;
        v.x = pack2(st[m0][k0],         st[m0][k0 + 1]);
        v.y = pack2(st[m0 + 8][k0],     st[m0 + 8][k0 + 1]);
        v.z = pack2(st[m0][k0 + 8],     st[m0][k0 + 9]);
        v.w = pack2(st[m0 + 8][k0 + 8], st[m0 + 8][k0 + 9]);
        *(uint4*)(dst + (size_t)s * 4) = v;
    }
}

// ---------------- pack Wk^T -> B-fragment-major fp16 ----------------
__global__ __launch_bounds__(256) void k_packW(const float* __restrict__ Wk)
{
    __shared__ float st[64][132];
    const int kc = blockIdx.x, h = blockIdx.y;
    const int tid = threadIdx.x;
    const float* src = Wk + (size_t)h * DS * EE + (size_t)kc * 64 * EE;
    for (int i = tid; i < 64 * 32; i += 256) {
        const int d = i >> 5, e4 = (i & 31) << 2;
        *(float4*)&st[d][e4] = *(const float4*)(src + (size_t)d * EE + e4);
    }
    __syncthreads();
    uint32_t* dst = g_Wkf + ((size_t)h * 8 + kc) * 4096;
    for (int s = tid; s < 2048; s += 256) {
        const int nb = s >> 7, ksb = (s >> 5) & 3, ln = s & 31;
        const int e = nb * 8 + (ln >> 2);
        const int d0 = ksb * 16 + (ln & 3) * 2;
        uint2 v;
        v.x = pack2(st[d0][e],     st[d0 + 1][e]);
        v.y = pack2(st[d0 + 8][e], st[d0 + 9][e]);
        *(uint2*)(dst + (size_t)s * 2) = v;
    }
}

// ---------------- projection kernel (fp16 mma, cp.async double-buffered; R12 form) ----------------
#define PROJ_SMEM 69632

__global__ __launch_bounds__(256, 2) void k_proj(const float* __restrict__ bk)
{
    extern __shared__ uint32_t sm[];
    const uint32_t smb = smem_u32(sm);
    const int tid = threadIdx.x, w = tid >> 5, lane = tid & 31;
    const int gg = lane >> 2, tig = lane & 3;
    const int wm = w >> 2, wn = w & 3;
    const int mt = blockIdx.x;
    const int h = blockIdx.y >> 3, b = blockIdx.y & 7;
    const int kind = blockIdx.z;

    const uint32_t* Asrc = g_Sf + (((size_t)b * 8 + mt) * 8) * 4096;
    const uint32_t* Bsrc = (kind ? g_Wvf : g_Wkf) + (size_t)h * 8 * 4096;

    float acc[4][4][4];
#pragma unroll
    for (int mi = 0; mi < 4; mi++)
#pragma unroll
        for (int ni = 0; ni < 4; ni++)
#pragma unroll
            for (int q = 0; q < 4; q++) acc[mi][ni][q] = 0.f;

    cp_chunk(smb, 0,    Asrc, tid);
    cp_chunk(smb, 8192, Bsrc, tid);
    cp_commit();

    for (int kc = 0; kc < 8; kc++) {
        if (kc < 7) {
            cp_chunk(smb, ((kc + 1) & 1) * 4096,        Asrc + (size_t)(kc + 1) * 4096, tid);
            cp_chunk(smb, 8192 + ((kc + 1) & 1) * 4096, Bsrc + (size_t)(kc + 1) * 4096, tid);
            cp_commit();
            asm volatile("cp.async.wait_group 1;" ::: "memory");
        } else {
            asm volatile("cp.async.wait_group 0;" ::: "memory");
        }
        __syncthreads();
        const uint32_t* Ab = sm + (kc & 1) * 4096;
        const uint32_t* Bb = sm + 8192 + (kc & 1) * 4096;
#pragma unroll
        for (int ksb = 0; ksb < 4; ksb++) {
            uint32_t af[4][4], bf[4][2];
#pragma unroll
            for (int mi = 0; mi < 4; mi++)
                *(uint4*)af[mi] = *(const uint4*)(Ab + (((wm * 4 + mi) * 4 + ksb) * 32 + lane) * 4);
#pragma unroll
            for (int ni = 0; ni < 4; ni++)
                *(uint2*)bf[ni] = *(const uint2*)(Bb + (((wn * 4 + ni) * 4 + ksb) * 32 + lane) * 2);
#pragma unroll
            for (int mi = 0; mi < 4; mi++)
#pragma unroll
                for (int ni = 0; ni < 4; ni++)
                    mma16(acc[mi][ni], af[mi], bf[ni]);
        }
        __syncthreads();
    }

    const float kscale = 0.08838834764831845f;   // 1/sqrt(128), folded into K

    if (kind == 0) {
        // DIRECT register->global epilogue for K (lane mapping is identity)
        uint32_t* dst = g_K + ((size_t)(h * BB + b) * 16 + mt * 2 + wm) * 4096;
#pragma unroll
        for (int mi = 0; mi < 4; mi++) {
#pragma unroll
            for (int ni2 = 0; ni2 < 2; ni2++) {
                const int ksb = wn * 2 + ni2;
                const int cc0 = wn * 32 + ni2 * 16 + 2 * tig;
                const int cc1 = cc0 + 8;
                const float b00 = bk[h * EE + cc0], b01 = bk[h * EE + cc0 + 1];
                const float b10 = bk[h * EE + cc1], b11 = bk[h * EE + cc1 + 1];
                const float* a0 = acc[mi][2 * ni2];
                const float* a1 = acc[mi][2 * ni2 + 1];
                uint2 v0, v1;
                v0.x = pack2((a0[0] + b00) * kscale, (a0[1] + b01) * kscale);
                v0.y = pack2((a1[0] + b10) * kscale, (a1[1] + b11) * kscale);
                v1.x = pack2((a0[2] + b00) * kscale, (a0[3] + b01) * kscale);
                v1.y = pack2((a1[2] + b10) * kscale, (a1[3] + b11) * kscale);
                *(uint2*)(dst + (((2 * mi) * 8 + ksb) * 32 + lane) * 2) = v0;
                *(uint2*)(dst + (((2 * mi + 1) * 8 + ksb) * 32 + lane) * 2) = v1;
            }
        }
    } else {
        // V' needs a transpose -> stage fp32 [128][131] then pack
        float* st = (float*)sm;
#pragma unroll
        for (int mi = 0; mi < 4; mi++) {
            const int r = wm * 64 + mi * 16 + gg;
#pragma unroll
            for (int ni = 0; ni < 4; ni++) {
                const int cc = wn * 32 + ni * 8 + 2 * tig;
                st[r * 131 + cc]           = acc[mi][ni][0];
                st[r * 131 + cc + 1]       = acc[mi][ni][1];
                st[(r + 8) * 131 + cc]     = acc[mi][ni][2];
                st[(r + 8) * 131 + cc + 1] = acc[mi][ni][3];
            }
        }
        __syncthreads();
        uint32_t* dst = g_Vt + ((size_t)(h * BB + b) * 16 + mt * 2) * 4096;
        for (int s = tid; s < 4096; s += 256) {
            const int lc = s >> 11, rem = s & 2047;
            const int nb = rem >> 7, ksb = (rem >> 5) & 3, ln = rem & 31;
            const int e = nb * 8 + (ln >> 2);
            const int t0 = lc * 64 + ksb * 16 + (ln & 3) * 2;
            uint2 v;
            v.x = pack2(st[t0 * 131 + e],       st[(t0 + 1) * 131 + e]);
            v.y = pack2(st[(t0 + 8) * 131 + e], st[(t0 + 9) * 131 + e]);
            *(uint2*)(dst + (size_t)lc * 4096 + ((nb * 4 + ksb) * 32 + ln) * 2) = v;
        }
    }
}

// ---------------- fused attention kernel: 256-row Q tile, 2 bands/warp ----------------
// Each warp owns rows [w*32, w*32+32) as two 16-row bands; K/V B-fragments are
// loaded ONCE per (nb,ksb) and reused for both bands -> crossbar traffic halves.
// smem (u32): Qf [0,16384) | K0 [16384,20480) K1 [20480,24576) | V0 [24576,28672) V1 [28672,32768)
#define QF_OFF 0
#define KB_OFF 16384
#define VB_OFF 24576
#define ATTN_SMEM (32768 * 4)   // 131072 B, 1 CTA/SM

__global__ __launch_bounds__(256) void k_attn(const float* __restrict__ query)
{
    extern __shared__ uint32_t sm[];
    const uint32_t smb = smem_u32(sm);
    const int tid = threadIdx.x, w = tid >> 5, lane = tid & 31;
    const int gg = lane >> 2, tig = lane & 3;
    const int qt = blockIdx.x, b = blockIdx.y, h = blockIdx.z;
    const int q0 = qt * 256;

    const uint32_t* Ksrc = g_K  + (size_t)(h * BB + b) * 16 * 4096;
    const uint32_t* Vsrc = g_Vt + (size_t)(h * BB + b) * 16 * 4096;

    // prefetch chunk 0 (joint commit, R12 style)
    cp_chunk(smb, KB_OFF, Ksrc, tid);
    cp_chunk(smb, VB_OFF, Vsrc, tid);
    cp_commit();

    // warp-private Q fragment pack (both bands), straight from gmem; no barriers:
    // each lane writes and later reads exactly its own fragment slots.
#pragma unroll
    for (int bd = 0; bd < 2; bd++) {
        const float* qrow0 = query + ((size_t)(b * NLQ + q0 + w * 32 + bd * 16 + gg)) * EE;
        const float* qrow1 = qrow0 + 8 * EE;
#pragma unroll
        for (int ksb = 0; ksb < 8; ksb++) {
            const int k0 = ksb * 16 + tig * 2;
            const float2 a0 = *(const float2*)(qrow0 + k0);
            const float2 a1 = *(const float2*)(qrow1 + k0);
            const float2 a2 = *(const float2*)(qrow0 + k0 + 8);
            const float2 a3 = *(const float2*)(qrow1 + k0 + 8);
            uint4 v;
            v.x = pack2(a0.x, a0.y);
            v.y = pack2(a1.x, a1.y);
            v.z = pack2(a2.x, a2.y);
            v.w = pack2(a3.x, a3.y);
            *(uint4*)(sm + QF_OFF + (((w * 2 + bd) * 8 + ksb) * 32 + lane) * 4) = v;
        }
    }

    float oacc[2][16][4];
#pragma unroll
    for (int bd = 0; bd < 2; bd++)
#pragma unroll
        for (int nb = 0; nb < 16; nb++)
#pragma unroll
            for (int q = 0; q < 4; q++) oacc[bd][nb][q] = 0.f;
    float ls[2][2] = {{0.f, 0.f}, {0.f, 0.f}};   // per-tig partials per band

    for (int c = 0; c < 16; c++) {
        asm volatile("cp.async.wait_group 0;" ::: "memory");
        __syncthreads();   // chunk c visible; buffers (c+1)&1 free
        if (c < 15) {
            cp_chunk(smb, KB_OFF + ((c + 1) & 1) * 4096, Ksrc + (size_t)(c + 1) * 4096, tid);
            cp_chunk(smb, VB_OFF + ((c + 1) & 1) * 4096, Vsrc + (size_t)(c + 1) * 4096, tid);
            cp_commit();
        }
        const uint32_t* Kb = sm + KB_OFF + (c & 1) * 4096;
        const uint32_t* Vb = sm + VB_OFF + (c & 1) * 4096;

        // ---- S = Q K^T (fp16 acc), both bands share each K fragment ----
        uint32_t sacc[2][8][2];
#pragma unroll
        for (int bd = 0; bd < 2; bd++)
#pragma unroll
            for (int nb = 0; nb < 8; nb++) { sacc[bd][nb][0] = 0u; sacc[bd][nb][1] = 0u; }
#pragma unroll
        for (int ksb = 0; ksb < 8; ksb++) {
            uint32_t aq0[4], aq1[4];
            *(uint4*)aq0 = *(const uint4*)(sm + QF_OFF + (((w * 2 + 0) * 8 + ksb) * 32 + lane) * 4);
            *(uint4*)aq1 = *(const uint4*)(sm + QF_OFF + (((w * 2 + 1) * 8 + ksb) * 32 + lane) * 4);
#pragma unroll
            for (int nb = 0; nb < 8; nb++) {
                uint32_t bf[2];
                *(uint2*)bf = *(const uint2*)(Kb + ((nb * 8 + ksb) * 32 + lane) * 2);
                mma16h(sacc[0][nb], aq0, bf);
                mma16h(sacc[1][nb], aq1, bf);
            }
        }

        // ---- P = exp(S) in registers ----
        uint32_t pf[2][16];
#pragma unroll
        for (int bd = 0; bd < 2; bd++) {
#pragma unroll
            for (int nb = 0; nb < 8; nb++) {
                const float2 f0 = __half22float2(*reinterpret_cast<__half2*>(&sacc[bd][nb][0]));
                const float2 f1 = __half22float2(*reinterpret_cast<__half2*>(&sacc[bd][nb][1]));
                const float e0 = __expf(f0.x);
                const float e1 = __expf(f0.y);
                const float e2 = __expf(f1.x);
                const float e3 = __expf(f1.y);
                ls[bd][0] += e0 + e1;
                ls[bd][1] += e2 + e3;
                pf[bd][nb * 2]     = pack2(e0, e1);
                pf[bd][nb * 2 + 1] = pack2(e2, e3);
            }
        }

        // ---- O += P @ V' (fp32 acc), both bands share each V fragment ----
#pragma unroll
        for (int ksb = 0; ksb < 4; ksb++) {
            uint32_t af0[4] = { pf[0][ksb * 4], pf[0][ksb * 4 + 1],
                                pf[0][ksb * 4 + 2], pf[0][ksb * 4 + 3] };
            uint32_t af1[4] = { pf[1][ksb * 4], pf[1][ksb * 4 + 1],
                                pf[1][ksb * 4 + 2], pf[1][ksb * 4 + 3] };
#pragma unroll
            for (int nb = 0; nb < 16; nb++) {
                uint32_t bf[2];
                *(uint2*)bf = *(const uint2*)(Vb + ((nb * 4 + ksb) * 32 + lane) * 2);
                mma16(oacc[0][nb], af0, bf);
                mma16(oacc[1][nb], af1, bf);
            }
        }
    }

    // deferred shuffle reductions + epilogue per band
    uint32_t* Op = g_OpartH + ((size_t)(h * BB + b) * NLQ + q0) * 64;
#pragma unroll
    for (int bd = 0; bd < 2; bd++) {
        float l0 = ls[bd][0], l1 = ls[bd][1];
        l0 += __shfl_xor_sync(0xffffffffu, l0, 1);
        l0 += __shfl_xor_sync(0xffffffffu, l0, 2);
        l1 += __shfl_xor_sync(0xffffffffu, l1, 1);
        l1 += __shfl_xor_sync(0xffffffffu, l1, 2);
        const float i0 = 1.f / l0;
        const float i1 = 1.f / l1;
        const int r = w * 32 + bd * 16 + gg;
#pragma unroll
        for (int nb = 0; nb < 16; nb++) {
            const int cc = nb * 8 + 2 * tig;
            Op[(size_t)r * 64 + (cc >> 1)] =
                pack2(oacc[bd][nb][0] * i0, oacc[bd][nb][1] * i0);
            Op[(size_t)(r + 8) * 64 + (cc >> 1)] =
                pack2(oacc[bd][nb][2] * i1, oacc[bd][nb][3] * i1);
        }
    }
}

// ---------------- final reduce over 32 fp16 head partials ----------------
__global__ void k_reduce(float* __restrict__ out)
{
    const size_t i4 = (size_t)blockIdx.x * blockDim.x + threadIdx.x;
    const size_t base = i4 * 4;             // 4 floats = 2 half2 words
    const int e = (int)(base & 127);
    float s0 = g_Cbias[e],     s1 = g_Cbias[e + 1];
    float s2 = g_Cbias[e + 2], s3 = g_Cbias[e + 3];
    const size_t st = (size_t)BB * NLQ * 64;
#pragma unroll
    for (int hh = 0; hh < HD; hh++) {
        const uint2 t = *(const uint2*)&g_OpartH[(size_t)hh * st + (base >> 1)];
        const __half2 a = *reinterpret_cast<const __half2*>(&t.x);
        const __half2 bb = *reinterpret_cast<const __half2*>(&t.y);
        const float2 fa = __half22float2(a);
        const float2 fb = __half22float2(bb);
        s0 += fa.x; s1 += fa.y; s2 += fb.x; s3 += fb.y;
    }
    *(float4*)&out[base] = make_float4(s0, s1, s2, s3);
}

// ---------------- launch ----------------
extern "C" void kernel_launch(void* const* d_in, const int* in_sizes, int n_in,
                              void* d_out, int out_size)
{
    const float* query  = (const float*)d_in[0];
    const float* states = (const float*)d_in[1];
    const float* Wk     = (const float*)d_in[2];
    const float* bk     = (const float*)d_in[3];
    const float* Wv     = (const float*)d_in[4];
    const float* bv     = (const float*)d_in[5];
    const float* Wo     = (const float*)d_in[6];
    const float* bo     = (const float*)d_in[7];
    float* out = (float*)d_out;

    cudaFuncSetAttribute(k_proj, cudaFuncAttributeMaxDynamicSharedMemorySize, PROJ_SMEM);
    cudaFuncSetAttribute(k_attn, cudaFuncAttributeMaxDynamicSharedMemorySize, ATTN_SMEM);

    k_wvwo<<<dim3(8, HD), 256>>>(Wv, Wo);
    k_cbias<<<EE, 32>>>(bv, Wo, bo);
    k_packS<<<dim3(8, 8, BB), 256>>>(states);
    k_packW<<<dim3(8, HD), 256>>>(Wk);
    k_proj<<<dim3(8, 256, 2), 256, PROJ_SMEM>>>(bk);
    k_attn<<<dim3(4, BB, HD), 256, ATTN_SMEM>>>(query);
    k_reduce<<<(BB * NLQ * EE / 4) / 256, 256>>>(out);
}

// round 15
// speedup vs baseline: 1.0563x; 1.0070x over previous
#include <cuda_runtime.h>
#include <cuda_fp16.h>
#include <cstdint>

#define HD 32
#define EE 128
#define DS 512
#define BB 8
#define NLQ 1024
#define NLK 1024

// ---------------- device scratch (allocation-free rule) ----------------
__device__ uint32_t g_K  [(size_t)HD * BB * 16 * 4096];  // K*scale+bk  [hb][chunk][nb8][ksb8][lane][2]
__device__ uint32_t g_Vt [(size_t)HD * BB * 16 * 4096];  // V'          [hb][chunk][nb16][ksb4][lane][2]
__device__ uint32_t g_Sf [(size_t)BB * 8 * 8 * 4096];    // states      [b][mt][kc][mb8][ksb4][lane][4]
__device__ uint32_t g_Wkf[(size_t)HD * 8 * 4096];        // Wk^T frag   [h][kc][nb16][ksb4][lane][2]
__device__ uint32_t g_Wvf[(size_t)HD * 8 * 4096];        // (Wv@Wo)^T frag
__device__ float g_Cbias[EE];
__device__ uint32_t g_OpartH[(size_t)BB * NLQ * HD * 64];  // fp16 head partials [b][q][h][64]

// ---------------- helpers ----------------
__device__ __forceinline__ uint32_t smem_u32(const void* p) {
    uint32_t a;
    asm("{ .reg .u64 t; cvta.to.shared.u64 t, %1; cvt.u32.u64 %0, t; }"
        : "=r"(a) : "l"(p));
    return a;
}
__device__ __forceinline__ uint32_t pack2(float a, float b) {
    __half2 h = __floats2half2_rn(a, b);
    return *reinterpret_cast<uint32_t*>(&h);
}
__device__ __forceinline__ void mma16(float* d, const uint32_t* a, const uint32_t* b) {
    asm volatile("mma.sync.aligned.m16n8k16.row.col.f32.f16.f16.f32 "
                 "{%0,%1,%2,%3}, {%4,%5,%6,%7}, {%8,%9}, {%0,%1,%2,%3};"
                 : "+f"(d[0]), "+f"(d[1]), "+f"(d[2]), "+f"(d[3])
                 : "r"(a[0]), "r"(a[1]), "r"(a[2]), "r"(a[3]),
                   "r"(b[0]), "r"(b[1]));
}
// fp16-accumulate variant (D/C in half2 words); used for S only
__device__ __forceinline__ void mma16h(uint32_t* d, const uint32_t* a, const uint32_t* b) {
    asm volatile("mma.sync.aligned.m16n8k16.row.col.f16.f16.f16.f16 "
                 "{%0,%1}, {%2,%3,%4,%5}, {%6,%7}, {%0,%1};"
                 : "+r"(d[0]), "+r"(d[1])
                 : "r"(a[0]), "r"(a[1]), "r"(a[2]), "r"(a[3]),
                   "r"(b[0]), "r"(b[1]));
}
__device__ __forceinline__ void cp16(uint32_t dst, const void* src) {
    asm volatile("cp.async.cg.shared.global [%0], [%1], 16;" :: "r"(dst), "l"(src));
}
__device__ __forceinline__ void cp_commit() {
    asm volatile("cp.async.commit_group;" ::: "memory");
}
// copy one 4096-u32 (16KB) fragment chunk, 256 threads
__device__ __forceinline__ void cp_chunk(uint32_t smb, int soff,
                                         const uint32_t* gsrc, int tid) {
#pragma unroll
    for (int i = 0; i < 4; i++) {
        const int idx = tid + i * 256;
        cp16(smb + (uint32_t)(soff + idx * 4) * 4, gsrc + (size_t)idx * 4);
    }
}

// ---------------- fused WvWo GEMM -> fragment-major pack ----------------
__global__ __launch_bounds__(256) void k_wvwo(const float* __restrict__ Wv,
                                              const float* __restrict__ Wo)
{
    __shared__ float As[64][16];
    __shared__ float Bs[16][128];
    __shared__ float st[64][132];
    const int mt = blockIdx.x, h = blockIdx.y;
    const float* A = Wv + (size_t)h * DS * EE + (size_t)mt * 64 * EE;
    const float* B = Wo + (size_t)h * EE * EE;
    const int tid = threadIdx.x;
    const int tx = tid & 15, ty = tid >> 4;
    float acc[4][8];
#pragma unroll
    for (int i = 0; i < 4; i++)
#pragma unroll
        for (int j = 0; j < 8; j++) acc[i][j] = 0.f;
    const int arow = tid >> 2, ac4 = (tid & 3) << 2;
    const int brow = tid >> 4, bc = (tid & 15) << 3;
    for (int k0 = 0; k0 < EE; k0 += 16) {
        __syncthreads();
        *(float4*)&As[arow][ac4] = *(const float4*)&A[(size_t)arow * EE + k0 + ac4];
        *(float4*)&Bs[brow][bc] = *(const float4*)&B[(size_t)(k0 + brow) * EE + bc];
        *(float4*)&Bs[brow][bc + 4] = *(const float4*)&B[(size_t)(k0 + brow) * EE + bc + 4];
        __syncthreads();
#pragma unroll
        for (int kk = 0; kk < 16; kk++) {
            float a[4], bb[8];
#pragma unroll
            for (int i = 0; i < 4; i++) a[i] = As[ty * 4 + i][kk];
#pragma unroll
            for (int j = 0; j < 8; j++) bb[j] = Bs[kk][tx + 16 * j];
#pragma unroll
            for (int i = 0; i < 4; i++)
#pragma unroll
                for (int j = 0; j < 8; j++) acc[i][j] += a[i] * bb[j];
        }
    }
#pragma unroll
    for (int i = 0; i < 4; i++)
#pragma unroll
        for (int j = 0; j < 8; j++)
            st[ty * 4 + i][tx + 16 * j] = acc[i][j];
    __syncthreads();
    uint32_t* dst = g_Wvf + ((size_t)h * 8 + mt) * 4096;
    for (int s = tid; s < 2048; s += 256) {
        const int nb = s >> 7, ksb = (s >> 5) & 3, ln = s & 31;
        const int e = nb * 8 + (ln >> 2);
        const int d0 = ksb * 16 + (ln & 3) * 2;
        uint2 v;
        v.x = pack2(st[d0][e],     st[d0 + 1][e]);
        v.y = pack2(st[d0 + 8][e], st[d0 + 9][e]);
        *(uint2*)(dst + (size_t)s * 2) = v;
    }
}

// fused constant bias: Cbias[e] = bo[e] + sum_h bv[h]@Wo_h[:,e]
__global__ void k_cbias(const float* __restrict__ bv, const float* __restrict__ Wo,
                        const float* __restrict__ bo)
{
    const int e = blockIdx.x, t = threadIdx.x;
    float acc = 0.f;
    for (int idx = t; idx < HD * EE; idx += 32)
        acc += bv[idx] * Wo[(size_t)idx * EE + e];
#pragma unroll
    for (int off = 16; off >= 1; off >>= 1)
        acc += __shfl_xor_sync(0xffffffffu, acc, off);
    if (t == 0) g_Cbias[e] = bo[e] + acc;
}

// ---------------- pack states -> A-fragment-major fp16 ----------------
__global__ __launch_bounds__(256) void k_packS(const float* __restrict__ states)
{
    __shared__ float st[128][68];
    const int kc = blockIdx.x, mt = blockIdx.y, b = blockIdx.z;
    const int tid = threadIdx.x;
    const float* src = states + ((size_t)b * NLK + mt * 128) * DS + kc * 64;
    for (int i = tid; i < 128 * 16; i += 256) {
        const int r = i >> 4, c4 = (i & 15) << 2;
        *(float4*)&st[r][c4] = *(const float4*)(src + (size_t)r * DS + c4);
    }
    __syncthreads();
    uint32_t* dst = g_Sf + (((size_t)b * 8 + mt) * 8 + kc) * 4096;
    for (int s = tid; s < 1024; s += 256) {
        const int mb = s >> 7, ksb = (s >> 5) & 3, ln = s & 31;
        const int m0 = mb * 16 + (ln >> 2);
        const int k0 = ksb * 16 + (ln & 3) * 2;
        uint4 v;
        v.x = pack2(st[m0][k0],         st[m0][k0 + 1]);
        v.y = pack2(st[m0 + 8][k0],     st[m0 + 8][k0 + 1]);
        v.z = pack2(st[m0][k0 + 8],     st[m0][k0 + 9]);
        v.w = pack2(st[m0 + 8][k0 + 8], st[m0 + 8][k0 + 9]);
        *(uint4*)(dst + (size_t)s * 4) = v;
    }
}

// ---------------- pack Wk^T -> B-fragment-major fp16 ----------------
__global__ __launch_bounds__(256) void k_packW(const float* __restrict__ Wk)
{
    __shared__ float st[64][132];
    const int kc = blockIdx.x, h = blockIdx.y;
    const int tid = threadIdx.x;
    const float* src = Wk + (size_t)h * DS * EE + (size_t)kc * 64 * EE;
    for (int i = tid; i < 64 * 32; i += 256) {
        const int d = i >> 5, e4 = (i & 31) << 2;
        *(float4*)&st[d][e4] = *(const float4*)(src + (size_t)d * EE + e4);
    }
    __syncthreads();
    uint32_t* dst = g_Wkf + ((size_t)h * 8 + kc) * 4096;
    for (int s = tid; s < 2048; s += 256) {
        const int nb = s >> 7, ksb = (s >> 5) & 3, ln = s & 31;
        const int e = nb * 8 + (ln >> 2);
        const int d0 = ksb * 16 + (ln & 3) * 2;
        uint2 v;
        v.x = pack2(st[d0][e],     st[d0 + 1][e]);
        v.y = pack2(st[d0 + 8][e], st[d0 + 9][e]);
        *(uint2*)(dst + (size_t)s * 2) = v;
    }
}

// ---------------- projection kernel (fp16 mma, cp.async double-buffered) ----------------
#define PROJ_SMEM 69632

__global__ __launch_bounds__(256, 2) void k_proj(const float* __restrict__ bk)
{
    extern __shared__ uint32_t sm[];
    const uint32_t smb = smem_u32(sm);
    const int tid = threadIdx.x, w = tid >> 5, lane = tid & 31;
    const int gg = lane >> 2, tig = lane & 3;
    const int wm = w >> 2, wn = w & 3;
    const int mt = blockIdx.x;
    const int h = blockIdx.y >> 3, b = blockIdx.y & 7;
    const int kind = blockIdx.z;

    const uint32_t* Asrc = g_Sf + (((size_t)b * 8 + mt) * 8) * 4096;
    const uint32_t* Bsrc = (kind ? g_Wvf : g_Wkf) + (size_t)h * 8 * 4096;

    float acc[4][4][4];
#pragma unroll
    for (int mi = 0; mi < 4; mi++)
#pragma unroll
        for (int ni = 0; ni < 4; ni++)
#pragma unroll
            for (int q = 0; q < 4; q++) acc[mi][ni][q] = 0.f;

    cp_chunk(smb, 0,    Asrc, tid);
    cp_chunk(smb, 8192, Bsrc, tid);
    cp_commit();

    for (int kc = 0; kc < 8; kc++) {
        if (kc < 7) {
            cp_chunk(smb, ((kc + 1) & 1) * 4096,        Asrc + (size_t)(kc + 1) * 4096, tid);
            cp_chunk(smb, 8192 + ((kc + 1) & 1) * 4096, Bsrc + (size_t)(kc + 1) * 4096, tid);
            cp_commit();
            asm volatile("cp.async.wait_group 1;" ::: "memory");
        } else {
            asm volatile("cp.async.wait_group 0;" ::: "memory");
        }
        __syncthreads();
        const uint32_t* Ab = sm + (kc & 1) * 4096;
        const uint32_t* Bb = sm + 8192 + (kc & 1) * 4096;
#pragma unroll
        for (int ksb = 0; ksb < 4; ksb++) {
            uint32_t af[4][4], bf[4][2];
#pragma unroll
            for (int mi = 0; mi < 4; mi++)
                *(uint4*)af[mi] = *(const uint4*)(Ab + (((wm * 4 + mi) * 4 + ksb) * 32 + lane) * 4);
#pragma unroll
            for (int ni = 0; ni < 4; ni++)
                *(uint2*)bf[ni] = *(const uint2*)(Bb + (((wn * 4 + ni) * 4 + ksb) * 32 + lane) * 2);
#pragma unroll
            for (int mi = 0; mi < 4; mi++)
#pragma unroll
                for (int ni = 0; ni < 4; ni++)
                    mma16(acc[mi][ni], af[mi], bf[ni]);
        }
        __syncthreads();
    }

    const float kscale = 0.08838834764831845f;   // 1/sqrt(128), folded into K

    if (kind == 0) {
        // DIRECT register->global epilogue for K (lane mapping is identity)
        uint32_t* dst = g_K + ((size_t)(h * BB + b) * 16 + mt * 2 + wm) * 4096;
#pragma unroll
        for (int mi = 0; mi < 4; mi++) {
#pragma unroll
            for (int ni2 = 0; ni2 < 2; ni2++) {
                const int ksb = wn * 2 + ni2;
                const int cc0 = wn * 32 + ni2 * 16 + 2 * tig;
                const int cc1 = cc0 + 8;
                const float b00 = bk[h * EE + cc0], b01 = bk[h * EE + cc0 + 1];
                const float b10 = bk[h * EE + cc1], b11 = bk[h * EE + cc1 + 1];
                const float* a0 = acc[mi][2 * ni2];
                const float* a1 = acc[mi][2 * ni2 + 1];
                uint2 v0, v1;
                v0.x = pack2((a0[0] + b00) * kscale, (a0[1] + b01) * kscale);
                v0.y = pack2((a1[0] + b10) * kscale, (a1[1] + b11) * kscale);
                v1.x = pack2((a0[2] + b00) * kscale, (a0[3] + b01) * kscale);
                v1.y = pack2((a1[2] + b10) * kscale, (a1[3] + b11) * kscale);
                *(uint2*)(dst + (((2 * mi) * 8 + ksb) * 32 + lane) * 2) = v0;
                *(uint2*)(dst + (((2 * mi + 1) * 8 + ksb) * 32 + lane) * 2) = v1;
            }
        }
    } else {
        // V' needs a transpose -> stage fp32 [128][131] then pack
        float* st = (float*)sm;
#pragma unroll
        for (int mi = 0; mi < 4; mi++) {
            const int r = wm * 64 + mi * 16 + gg;
#pragma unroll
            for (int ni = 0; ni < 4; ni++) {
                const int cc = wn * 32 + ni * 8 + 2 * tig;
                st[r * 131 + cc]           = acc[mi][ni][0];
                st[r * 131 + cc + 1]       = acc[mi][ni][1];
                st[(r + 8) * 131 + cc]     = acc[mi][ni][2];
                st[(r + 8) * 131 + cc + 1] = acc[mi][ni][3];
            }
        }
        __syncthreads();
        uint32_t* dst = g_Vt + ((size_t)(h * BB + b) * 16 + mt * 2) * 4096;
        for (int s = tid; s < 4096; s += 256) {
            const int lc = s >> 11, rem = s & 2047;
            const int nb = rem >> 7, ksb = (rem >> 5) & 3, ln = rem & 31;
            const int e = nb * 8 + (ln >> 2);
            const int t0 = lc * 64 + ksb * 16 + (ln & 3) * 2;
            uint2 v;
            v.x = pack2(st[t0 * 131 + e],       st[(t0 + 1) * 131 + e]);
            v.y = pack2(st[(t0 + 8) * 131 + e], st[(t0 + 9) * 131 + e]);
            *(uint2*)(dst + (size_t)lc * 4096 + ((nb * 4 + ksb) * 32 + ln) * 2) = v;
        }
    }
}

// ---------------- fused attention kernel: 256-row Q tile, 2 bands/warp ----------------
// Each warp owns rows [w*32, w*32+32) as two 16-row bands; K/V B-fragments are
// loaded ONCE per (nb,ksb) and reused for both bands -> crossbar traffic halves.
// smem (u32): Qf [0,16384) | K0 [16384,20480) K1 [20480,24576) | V0 [24576,28672) V1 [28672,32768)
#define QF_OFF 0
#define KB_OFF 16384
#define VB_OFF 24576
#define ATTN_SMEM (32768 * 4)   // 131072 B, 1 CTA/SM

__global__ __launch_bounds__(256) void k_attn(const float* __restrict__ query)
{
    extern __shared__ uint32_t sm[];
    const uint32_t smb = smem_u32(sm);
    const int tid = threadIdx.x, w = tid >> 5, lane = tid & 31;
    const int gg = lane >> 2, tig = lane & 3;
    const int qt = blockIdx.x, b = blockIdx.y, h = blockIdx.z;
    const int q0 = qt * 256;

    const uint32_t* Ksrc = g_K  + (size_t)(h * BB + b) * 16 * 4096;
    const uint32_t* Vsrc = g_Vt + (size_t)(h * BB + b) * 16 * 4096;

    // prefetch chunk 0 (joint commit)
    cp_chunk(smb, KB_OFF, Ksrc, tid);
    cp_chunk(smb, VB_OFF, Vsrc, tid);
    cp_commit();

    // warp-private Q fragment pack (both bands), straight from gmem; no barriers.
#pragma unroll
    for (int bd = 0; bd < 2; bd++) {
        const float* qrow0 = query + ((size_t)(b * NLQ + q0 + w * 32 + bd * 16 + gg)) * EE;
        const float* qrow1 = qrow0 + 8 * EE;
#pragma unroll
        for (int ksb = 0; ksb < 8; ksb++) {
            const int k0 = ksb * 16 + tig * 2;
            const float2 a0 = *(const float2*)(qrow0 + k0);
            const float2 a1 = *(const float2*)(qrow1 + k0);
            const float2 a2 = *(const float2*)(qrow0 + k0 + 8);
            const float2 a3 = *(const float2*)(qrow1 + k0 + 8);
            uint4 v;
            v.x = pack2(a0.x, a0.y);
            v.y = pack2(a1.x, a1.y);
            v.z = pack2(a2.x, a2.y);
            v.w = pack2(a3.x, a3.y);
            *(uint4*)(sm + QF_OFF + (((w * 2 + bd) * 8 + ksb) * 32 + lane) * 4) = v;
        }
    }

    float oacc[2][16][4];
#pragma unroll
    for (int bd = 0; bd < 2; bd++)
#pragma unroll
        for (int nb = 0; nb < 16; nb++)
#pragma unroll
            for (int q = 0; q < 4; q++) oacc[bd][nb][q] = 0.f;
    float ls[2][2] = {{0.f, 0.f}, {0.f, 0.f}};   // per-tig partials per band

    for (int c = 0; c < 16; c++) {
        asm volatile("cp.async.wait_group 0;" ::: "memory");
        __syncthreads();   // chunk c visible; buffers (c+1)&1 free
        if (c < 15) {
            cp_chunk(smb, KB_OFF + ((c + 1) & 1) * 4096, Ksrc + (size_t)(c + 1) * 4096, tid);
            cp_chunk(smb, VB_OFF + ((c + 1) & 1) * 4096, Vsrc + (size_t)(c + 1) * 4096, tid);
            cp_commit();
        }
        const uint32_t* Kb = sm + KB_OFF + (c & 1) * 4096;
        const uint32_t* Vb = sm + VB_OFF + (c & 1) * 4096;

        // ---- S = Q K^T (fp16 acc), both bands share each K fragment ----
        uint32_t sacc[2][8][2];
#pragma unroll
        for (int bd = 0; bd < 2; bd++)
#pragma unroll
            for (int nb = 0; nb < 8; nb++) { sacc[bd][nb][0] = 0u; sacc[bd][nb][1] = 0u; }
#pragma unroll
        for (int ksb = 0; ksb < 8; ksb++) {
            uint32_t aq0[4], aq1[4];
            *(uint4*)aq0 = *(const uint4*)(sm + QF_OFF + (((w * 2 + 0) * 8 + ksb) * 32 + lane) * 4);
            *(uint4*)aq1 = *(const uint4*)(sm + QF_OFF + (((w * 2 + 1) * 8 + ksb) * 32 + lane) * 4);
#pragma unroll
            for (int nb = 0; nb < 8; nb++) {
                uint32_t bf[2];
                *(uint2*)bf = *(const uint2*)(Kb + ((nb * 8 + ksb) * 32 + lane) * 2);
                mma16h(sacc[0][nb], aq0, bf);
                mma16h(sacc[1][nb], aq1, bf);
            }
        }

        // ---- P = exp(S) in registers ----
        uint32_t pf[2][16];
#pragma unroll
        for (int bd = 0; bd < 2; bd++) {
#pragma unroll
            for (int nb = 0; nb < 8; nb++) {
                const float2 f0 = __half22float2(*reinterpret_cast<__half2*>(&sacc[bd][nb][0]));
                const float2 f1 = __half22float2(*reinterpret_cast<__half2*>(&sacc[bd][nb][1]));
                const float e0 = __expf(f0.x);
                const float e1 = __expf(f0.y);
                const float e2 = __expf(f1.x);
                const float e3 = __expf(f1.y);
                ls[bd][0] += e0 + e1;
                ls[bd][1] += e2 + e3;
                pf[bd][nb * 2]     = pack2(e0, e1);
                pf[bd][nb * 2 + 1] = pack2(e2, e3);
            }
        }

        // ---- O += P @ V' (fp32 acc), both bands share each V fragment ----
#pragma unroll
        for (int ksb = 0; ksb < 4; ksb++) {
            uint32_t af0[4] = { pf[0][ksb * 4], pf[0][ksb * 4 + 1],
                                pf[0][ksb * 4 + 2], pf[0][ksb * 4 + 3] };
            uint32_t af1[4] = { pf[1][ksb * 4], pf[1][ksb * 4 + 1],
                                pf[1][ksb * 4 + 2], pf[1][ksb * 4 + 3] };
#pragma unroll
            for (int nb = 0; nb < 16; nb++) {
                uint32_t bf[2];
                *(uint2*)bf = *(const uint2*)(Vb + ((nb * 4 + ksb) * 32 + lane) * 2);
                mma16(oacc[0][nb], af0, bf);
                mma16(oacc[1][nb], af1, bf);
            }
        }
    }

    // deferred shuffle reductions + epilogue per band
    // NEW layout: g_OpartH[b][q][h][64] -> head-contiguous for streaming reduce
#pragma unroll
    for (int bd = 0; bd < 2; bd++) {
        float l0 = ls[bd][0], l1 = ls[bd][1];
        l0 += __shfl_xor_sync(0xffffffffu, l0, 1);
        l0 += __shfl_xor_sync(0xffffffffu, l0, 2);
        l1 += __shfl_xor_sync(0xffffffffu, l1, 1);
        l1 += __shfl_xor_sync(0xffffffffu, l1, 2);
        const float i0 = 1.f / l0;
        const float i1 = 1.f / l1;
        const int r = w * 32 + bd * 16 + gg;
        uint32_t* Op0 = g_OpartH + (((size_t)(b * NLQ + q0 + r)) * HD + h) * 64;
        uint32_t* Op1 = g_OpartH + (((size_t)(b * NLQ + q0 + r + 8)) * HD + h) * 64;
#pragma unroll
        for (int nb = 0; nb < 16; nb++) {
            const int cc = nb * 8 + 2 * tig;
            Op0[cc >> 1] = pack2(oacc[bd][nb][0] * i0, oacc[bd][nb][1] * i0);
            Op1[cc >> 1] = pack2(oacc[bd][nb][2] * i1, oacc[bd][nb][3] * i1);
        }
    }
}

// ---------------- final reduce over 32 fp16 head partials (streaming) ----------------
__global__ void k_reduce(float* __restrict__ out)
{
    const size_t i4 = (size_t)blockIdx.x * blockDim.x + threadIdx.x;
    const size_t base = i4 * 4;             // 4 floats = 2 half2 words
    const int e = (int)(base & 127);
    const size_t bq = base >> 7;            // (b*NLQ + q)
    float s0 = g_Cbias[e],     s1 = g_Cbias[e + 1];
    float s2 = g_Cbias[e + 2], s3 = g_Cbias[e + 3];
    const uint32_t* src = g_OpartH + bq * HD * 64 + (e >> 1);
#pragma unroll
    for (int hh = 0; hh < HD; hh++) {
        const uint2 t = *(const uint2*)(src + (size_t)hh * 64);
        const __half2 a = *reinterpret_cast<const __half2*>(&t.x);
        const __half2 bb = *reinterpret_cast<const __half2*>(&t.y);
        const float2 fa = __half22float2(a);
        const float2 fb = __half22float2(bb);
        s0 += fa.x; s1 += fa.y; s2 += fb.x; s3 += fb.y;
    }
    *(float4*)&out[base] = make_float4(s0, s1, s2, s3);
}

// ---------------- launch ----------------
extern "C" void kernel_launch(void* const* d_in, const int* in_sizes, int n_in,
                              void* d_out, int out_size)
{
    const float* query  = (const float*)d_in[0];
    const float* states = (const float*)d_in[1];
    const float* Wk     = (const float*)d_in[2];
    const float* bk     = (const float*)d_in[3];
    const float* Wv     = (const float*)d_in[4];
    const float* bv     = (const float*)d_in[5];
    const float* Wo     = (const float*)d_in[6];
    const float* bo     = (const float*)d_in[7];
    float* out = (float*)d_out;

    cudaFuncSetAttribute(k_proj, cudaFuncAttributeMaxDynamicSharedMemorySize, PROJ_SMEM);
    cudaFuncSetAttribute(k_attn, cudaFuncAttributeMaxDynamicSharedMemorySize, ATTN_SMEM);

    k_wvwo<<<dim3(8, HD), 256>>>(Wv, Wo);
    k_cbias<<<EE, 32>>>(bv, Wo, bo);
    k_packS<<<dim3(8, 8, BB), 256>>>(states);
    k_packW<<<dim3(8, HD), 256>>>(Wk);
    k_proj<<<dim3(8, 256, 2), 256, PROJ_SMEM>>>(bk);
    k_attn<<<dim3(4, BB, HD), 256, ATTN_SMEM>>>(query);
    k_reduce<<<(BB * NLQ * EE / 4) / 256, 256>>>(out);
}